// round 12
// baseline (speedup 1.0000x reference)
#include <cuda_runtime.h>
#include <cuda_fp16.h>
#include <stdint.h>
#include <math.h>

#define N_PTS   32768
#define KCODES  2048
#define DIM     128
#define BM      128
#define BN      32
#define NTILES  (KCODES / BN)        // 64
#define TEMP_INV (1.0f/0.9f)

// smem float offsets
#define A_S    0                     // 16384 floats: A hi, fragment order (64KB)
#define B_S    16384                 // 2 stages x 4096 floats (32KB)
#define SMEM_FLOATS 24576            // 96KB
// post-mainloop reuse inside B region:
#define RED_V  16384                 // [128][8]
#define RED_I  17408                 // [128][8]
#define SIDX   18432                 // [128]
#define MAXV   18560                 // [128]
#define ZINV   18688                 // [8]
#define BINS   18696                 // [2048]

__device__ __half g_conf[(size_t)N_PTS * KCODES]; // 128 MB conf_hh spill (fp16)
__device__ float  g_esq[KCODES];
__device__ float  g_clsum[KCODES];
__device__ float  g_bhi[KCODES * DIM];            // B tf32-hi, fragment order, tile-major

__device__ __forceinline__ float tf32r(float a) {
    float r; asm("cvt.rna.tf32.f32 %0, %1;" : "=f"(r) : "f"(a)); return r;
}
__device__ __forceinline__ void cp_async16(uint32_t saddr, const void* gptr) {
    asm volatile("cp.async.cg.shared.global [%0], [%1], 16;" :: "r"(saddr), "l"(gptr));
}

#define MMA_TF32(d, a, b) \
    asm volatile("mma.sync.aligned.m16n8k8.row.col.f32.tf32.tf32.f32 " \
        "{%0,%1,%2,%3},{%4,%5,%6,%7},{%8,%9},{%0,%1,%2,%3};" \
        : "+f"((d)[0]), "+f"((d)[1]), "+f"((d)[2]), "+f"((d)[3]) \
        : "r"(__float_as_uint((a)[0])), "r"(__float_as_uint((a)[1])), \
          "r"(__float_as_uint((a)[2])), "r"(__float_as_uint((a)[3])), \
          "r"(__float_as_uint((b)[0])), "r"(__float_as_uint((b)[1])))

// Warp-cooperative exact fp32 confidence: 2*dot(x_n, e_k) - esq[k].
// All lanes return the same value (xor-reduce), so comparisons are
// warp-uniform and internally consistent across candidates.
__device__ __forceinline__ float warp_conf(float4 xv, const float* __restrict__ embed,
                                           int k, int lane) {
    float4 ev = ((const float4*)(embed + (size_t)k * DIM))[lane];
    float s = xv.x * ev.x;
    s = fmaf(xv.y, ev.y, s);
    s = fmaf(xv.z, ev.z, s);
    s = fmaf(xv.w, ev.w, s);
    #pragma unroll
    for (int o = 16; o > 0; o >>= 1) s += __shfl_xor_sync(0xffffffffu, s, o);
    return fmaf(2.f, s, -__ldg(&g_esq[k]));
}

// ---------------------------------------------------------------------------
// Kernel 1: e_sq per code, zero class accumulators, write tf32-hi(embed)
// into MMA fragment order, tile-major (BN=32). (R5-proven mapping.)
// ---------------------------------------------------------------------------
__global__ void prep_kernel(const float* __restrict__ embed) {
    const int tid  = blockIdx.x * blockDim.x + threadIdx.x;  // 0..65535
    const int lane = tid & 31;
    const int warp = tid >> 5;
    if (tid < KCODES) g_clsum[tid] = 0.f;

    {   // e_sq, warp per code
        const float* row = embed + (size_t)warp * DIM;
        float s = 0.f;
        #pragma unroll
        for (int i = 0; i < 4; ++i) { float v = row[lane + 32 * i]; s = fmaf(v, v, s); }
        #pragma unroll
        for (int o = 16; o > 0; o >>= 1) s += __shfl_down_sync(0xffffffffu, s, o);
        if (lane == 0) g_esq[warp] = s;
    }

    {   // B hi fragment-order scatter: one float4 per thread
        float4 v = ((const float4*)embed)[tid];
        const int n   = tid >> 5;
        const int k4  = tid & 31;
        const int ct  = n >> 5;
        const int wn  = (n >> 4) & 1;
        const int nt  = (n >> 3) & 1;
        const int gid = n & 7;
        const int ks  = k4 >> 1;
        const int slot = k4 & 1;
        float a4[4] = {v.x, v.y, v.z, v.w};
        #pragma unroll
        for (int j = 0; j < 4; ++j) {
            size_t o = (size_t)ct * 4096 +
                       ((size_t)(((wn * 2 + nt) * 16 + ks) * 32 + gid * 4 + j)) * 2 + slot;
            g_bhi[o] = tf32r(a4[j]);
        }
    }
}

// ---------------------------------------------------------------------------
// Kernel 2: TF32 hi*hi GEMM + fp16 conf spill + argmax w/ warp-cooperative
// exact rescue + fused softmax + gather. 96KB smem -> 2 CTAs/SM, 1 wave.
// ---------------------------------------------------------------------------
__global__ void __launch_bounds__(256, 2)
gemm_kernel(const float* __restrict__ x,
            const float* __restrict__ embed,
            float* __restrict__ out_q,
            float* __restrict__ out_ind) {
    extern __shared__ float sm[];

    const int tid  = threadIdx.x;
    const int lane = tid & 31;
    const int w    = tid >> 5;
    const int wm   = w >> 1;          // 0..3: 32-point slab
    const int wn   = w & 1;           // 0..1: 16-code slab
    const int n0   = blockIdx.x * BM;

    const uint32_t b_s = (uint32_t)__cvta_generic_to_shared(sm + B_S);

    // ---- issue B tile 0 copy ----
    {
        const float4* g4 = (const float4*)g_bhi;
        #pragma unroll
        for (int i = 0; i < 4; ++i)
            cp_async16(b_s + (i * 256 + tid) * 16, &g4[i * 256 + tid]);
        asm volatile("cp.async.commit_group;");
    }

    // ---- A hi: tf32(2*x) directly into fragment order ----
    {
        const float4* x4 = (const float4*)(x + (size_t)n0 * DIM);
        #pragma unroll
        for (int t = 0; t < 16; ++t) {
            int idx = t * 256 + tid;
            int m  = idx >> 5;
            int k4 = idx & 31;
            float4 v = x4[idx];
            float a4[4] = {2.f * v.x, 2.f * v.y, 2.f * v.z, 2.f * v.w};
            int r    = m & 15;
            int base = (((m >> 4) * 16 + (k4 >> 1)) * 32) * 4;
            int sl   = (r >> 3) + ((k4 & 1) << 1);
            #pragma unroll
            for (int j = 0; j < 4; ++j)
                sm[A_S + base + ((r & 7) * 4 + j) * 4 + sl] = tf32r(a4[j]);
        }
    }

    float runv[4];
    int   runi[4];
    #pragma unroll
    for (int i = 0; i < 4; ++i) { runv[i] = -3.0e38f; runi[i] = 0; }

    for (int ct = 0; ct < NTILES; ++ct) {
        if (ct + 1 < NTILES) {
            const float4* g4 = (const float4*)(g_bhi + (size_t)(ct + 1) * 4096);
            uint32_t dst = b_s + (uint32_t)(((ct + 1) & 1) * 16384);
            #pragma unroll
            for (int i = 0; i < 4; ++i)
                cp_async16(dst + (i * 256 + tid) * 16, &g4[i * 256 + tid]);
            asm volatile("cp.async.commit_group;");
            asm volatile("cp.async.wait_group 1;");
        } else {
            asm volatile("cp.async.wait_group 0;");
        }
        __syncthreads();                      // stage (ct&1) visible to all warps

        const float* b_hi = sm + B_S + (ct & 1) * 4096;

        float acc[2][2][4];
        #pragma unroll
        for (int mt = 0; mt < 2; ++mt)
            #pragma unroll
            for (int nt = 0; nt < 2; ++nt)
                #pragma unroll
                for (int r = 0; r < 4; ++r) acc[mt][nt][r] = 0.f;

        #pragma unroll
        for (int ks = 0; ks < 16; ++ks) {
            float4 ah4[2];
            #pragma unroll
            for (int mt = 0; mt < 2; ++mt) {
                int ab = (((wm * 2 + mt) * 16 + ks) * 32 + lane) * 4;
                ah4[mt] = *(const float4*)&sm[A_S + ab];
            }
            float2 bh2[2];
            #pragma unroll
            for (int nt = 0; nt < 2; ++nt) {
                int bb = (((wn * 2 + nt) * 16 + ks) * 32 + lane) * 2;
                bh2[nt] = *(const float2*)&b_hi[bb];
            }
            #pragma unroll
            for (int mt = 0; mt < 2; ++mt)
                #pragma unroll
                for (int nt = 0; nt < 2; ++nt)
                    MMA_TF32(acc[mt][nt], (&ah4[mt].x), (&bh2[nt].x));   // hi*hi only
        }

        // ---- epilogue: conf_hh = acc - esq, running argmax, fp16 spill ----
        const int c0 = ct * BN;
        #pragma unroll
        for (int nt = 0; nt < 2; ++nt) {
            int cb = c0 + wn * 16 + nt * 8 + 2 * (lane & 3);
            float e0 = __ldg(&g_esq[cb]);
            float e1 = __ldg(&g_esq[cb + 1]);
            #pragma unroll
            for (int mt = 0; mt < 2; ++mt) {
                #pragma unroll
                for (int h = 0; h < 2; ++h) {
                    int slot = mt * 2 + h;
                    int row  = n0 + wm * 32 + mt * 16 + (lane >> 2) + h * 8;
                    float v0 = acc[mt][nt][2 * h + 0] - e0;
                    float v1 = acc[mt][nt][2 * h + 1] - e1;
                    if (v0 > runv[slot]) { runv[slot] = v0; runi[slot] = cb; }
                    if (v1 > runv[slot]) { runv[slot] = v1; runi[slot] = cb + 1; }
                    *(__half2*)&g_conf[(size_t)row * KCODES + cb] =
                        __floats2half2_rn(v0, v1);
                }
            }
        }
        __syncthreads();                      // stage safe to overwrite
    }

    // ---- cross-thread argmax reduction (8 contributors per point) ----
    float* red_v  = sm + RED_V;
    int*   red_i  = (int*)(sm + RED_I);
    int*   sidx   = (int*)(sm + SIDX);
    float* maxv_s = sm + MAXV;
    float* zinv   = sm + ZINV;
    float* bins_s = sm + BINS;
    #pragma unroll
    for (int mt = 0; mt < 2; ++mt)
        #pragma unroll
        for (int h = 0; h < 2; ++h) {
            int slot = mt * 2 + h;
            int rloc = wm * 32 + mt * 16 + (lane >> 2) + h * 8;
            int cidx = wn * 4 + (lane & 3);
            red_v[rloc * 8 + cidx] = runv[slot];
            red_i[rloc * 8 + cidx] = runi[slot];
        }
    __syncthreads();
    if (tid < BM) {
        float bv = red_v[tid * 8];
        int   bi = red_i[tid * 8];
        #pragma unroll
        for (int t = 1; t < 8; ++t) {
            float v  = red_v[tid * 8 + t];
            int   ii = red_i[tid * 8 + t];
            if (v > bv || (v == bv && ii < bi)) { bv = v; bi = ii; }
        }
        maxv_s[tid] = bv;
        sidx[tid]   = bi;
    }
    if (tid < KCODES / 8) {
        #pragma unroll
        for (int r = 0; r < 8; ++r) bins_s[r * 256 + tid] = 0.f;
    }
    __syncthreads();

    // ---- fused softmax on fp16 conf (warp per point) + warp-coop rescue ----
    {
        float* eb = sm + A_S;              // [8][KCODES], A region reused
        for (int it = 0; it < BM / 8; ++it) {
            const int pl = it * 8 + w;
            const float m = maxv_s[pl];
            const int   am = sidx[pl];
            const float thresh = m - 2.0f;     // covers hh err + fp16 storage err
            const uint4* row16 = (const uint4*)&g_conf[(size_t)(n0 + pl) * KCODES];

            uint32_t cm0 = 0u, cm1 = 0u;   // candidate bitmask, 64 bits (j*8+t)
            float z = 0.f;
            #pragma unroll
            for (int j = 0; j < 8; ++j) {
                uint4 u = row16[j * 32 + lane];    // 8 halves: k = j*256+lane*8+..
                float c[8];
                {
                    float2 f0 = __half22float2(*(__half2*)&u.x);
                    float2 f1 = __half22float2(*(__half2*)&u.y);
                    float2 f2 = __half22float2(*(__half2*)&u.z);
                    float2 f3 = __half22float2(*(__half2*)&u.w);
                    c[0] = f0.x; c[1] = f0.y; c[2] = f1.x; c[3] = f1.y;
                    c[4] = f2.x; c[5] = f2.y; c[6] = f3.x; c[7] = f3.y;
                }
                int kb = j * 256 + lane * 8;
                float e[8];
                uint32_t mbits = 0u;
                #pragma unroll
                for (int t = 0; t < 8; ++t) {
                    e[t] = __expf((c[t] - m) * TEMP_INV);
                    z += e[t];
                    if (c[t] >= thresh && kb + t != am) mbits |= (1u << t);
                }
                *(float4*)&eb[w * KCODES + kb]     = make_float4(e[0], e[1], e[2], e[3]);
                *(float4*)&eb[w * KCODES + kb + 4] = make_float4(e[4], e[5], e[6], e[7]);
                if (j < 4) cm0 |= mbits << (j * 8);
                else       cm1 |= mbits << ((j - 4) * 8);
            }
            #pragma unroll
            for (int o = 16; o > 0; o >>= 1) z += __shfl_xor_sync(0xffffffffu, z, o);
            if (lane == 0) zinv[w] = 1.f / z;

            // rescue: warp-cooperative exact fp32 comparison among candidates
            if (__ballot_sync(0xffffffffu, (cm0 | cm1) != 0u) != 0u) {
                float4 xv = ((const float4*)(x + (size_t)(n0 + pl) * DIM))[lane];
                float bv = warp_conf(xv, embed, am, lane);   // exact winner value
                int   bi = am;
                for (;;) {
                    uint32_t have = __ballot_sync(0xffffffffu, (cm0 | cm1) != 0u);
                    if (!have) break;
                    int src = __ffs(have) - 1;
                    int kc = 0;
                    if (lane == src) {
                        if (cm0) {
                            int b = __ffs(cm0) - 1; cm0 &= cm0 - 1;
                            kc = (b >> 3) * 256 + lane * 8 + (b & 7);
                        } else {
                            int b = __ffs(cm1) - 1; cm1 &= cm1 - 1;
                            kc = 1024 + (b >> 3) * 256 + lane * 8 + (b & 7);
                        }
                    }
                    kc = __shfl_sync(0xffffffffu, kc, src);
                    float v = warp_conf(xv, embed, kc, lane);
                    if (v > bv || (v == bv && kc < bi)) { bv = v; bi = kc; }
                }
                if (lane == 0) sidx[pl] = bi;
            }
            __syncthreads();

            for (int k = tid; k < KCODES; k += 256) {
                float s = 0.f;
                #pragma unroll
                for (int ww = 0; ww < 8; ++ww) s = fmaf(eb[ww * KCODES + k], zinv[ww], s);
                bins_s[k] += s;
            }
            __syncthreads();
        }
    }

    // ---- ind write + gather with rescued indices + bins flush ----
    if (tid < BM) out_ind[n0 + tid] = (float)sidx[tid];
    {
        const float4* e4 = (const float4*)embed;
        float4*       q4 = (float4*)out_q;
        for (int p = w; p < BM; p += 8) {
            int idx = sidx[p];
            q4[(size_t)(n0 + p) * 32 + lane] = e4[(size_t)idx * 32 + lane];
        }
    }
    for (int k = tid; k < KCODES; k += 256) atomicAdd(&g_clsum[k], bins_s[k]);
}

// ---------------------------------------------------------------------------
// Kernel 3: diversity loss = sum_k p_k * log(p_k + eps).
// ---------------------------------------------------------------------------
__global__ void loss_kernel(float* __restrict__ out_loss) {
    __shared__ float red[256];
    const int tid = threadIdx.x;
    float acc = 0.f;
    for (int k = tid; k < KCODES; k += 256) {
        float p = g_clsum[k] * (1.0f / (float)N_PTS);
        acc += p * __logf(p + 1e-6f);
    }
    red[tid] = acc;
    __syncthreads();
    for (int s = 128; s > 0; s >>= 1) {
        if (tid < s) red[tid] += red[tid + s];
        __syncthreads();
    }
    if (tid == 0) *out_loss = red[0];
}

// ---------------------------------------------------------------------------
extern "C" void kernel_launch(void* const* d_in, const int* in_sizes, int n_in,
                              void* d_out, int out_size) {
    const float* x     = (const float*)d_in[0];
    const float* embed = (const float*)d_in[1];
    float* out      = (float*)d_out;
    float* out_q    = out;                                   // N*DIM
    float* out_ind  = out + (size_t)N_PTS * DIM;             // N
    float* out_loss = out + (size_t)N_PTS * DIM + N_PTS;     // 1

    const int gemm_smem = SMEM_FLOATS * (int)sizeof(float);  // 96 KB
    cudaFuncSetAttribute(gemm_kernel, cudaFuncAttributeMaxDynamicSharedMemorySize, gemm_smem);

    prep_kernel <<<256, 256>>>(embed);
    gemm_kernel <<<N_PTS / BM, 256, gemm_smem>>>(x, embed, out_q, out_ind);
    loss_kernel <<<1, 256>>>(out_loss);
}

// round 13
// speedup vs baseline: 1.5184x; 1.5184x over previous
#include <cuda_runtime.h>
#include <cuda_fp16.h>
#include <stdint.h>
#include <math.h>

#define N_PTS   32768
#define KCODES  2048
#define DIM     128
#define BM      128
#define BN      32
#define NTILES  (KCODES / BN)        // 64
#define TEMP_INV (1.0f/0.9f)

// smem float offsets
#define AF_S   0                     // A fragment staging: 8192 u32 (32KB)
#define B_S    8192                  // 2 stages x 2048 floats-worth (fp16 frags, 8KB each)
// post-mainloop reuse:
#define EB_S   0                     // [8][KCODES] floats (64KB)
#define RED_V  16384                 // [128][8]
#define RED_I  17408                 // [128][8]
#define SIDX   18432                 // [128]
#define MAXV   18560                 // [128]
#define ZINV   18688                 // [8]
#define BINS   18696                 // [2048]
#define SMEM_FLOATS 20992            // ~84KB

__device__ __half    g_conf[(size_t)N_PTS * KCODES]; // 128 MB conf spill (fp16)
__device__ float     g_esq[KCODES];
__device__ float     g_clsum[KCODES];
__device__ uint32_t  g_bh[KCODES * DIM / 2];         // B fp16 fragment order, tile-major (512KB)

__device__ __forceinline__ void cp_async16(uint32_t saddr, const void* gptr) {
    asm volatile("cp.async.cg.shared.global [%0], [%1], 16;" :: "r"(saddr), "l"(gptr));
}

#define MMA_F16(d, a, b) \
    asm volatile("mma.sync.aligned.m16n8k16.row.col.f32.f16.f16.f32 " \
        "{%0,%1,%2,%3},{%4,%5,%6,%7},{%8,%9},{%0,%1,%2,%3};" \
        : "+f"((d)[0]), "+f"((d)[1]), "+f"((d)[2]), "+f"((d)[3]) \
        : "r"((a).x), "r"((a).y), "r"((a).z), "r"((a).w), \
          "r"((b).x), "r"((b).y))

// Warp-cooperative exact fp32 confidence: 2*dot(x_n, e_k) - esq[k].
__device__ __forceinline__ float warp_conf(float4 xv, const float* __restrict__ embed,
                                           int k, int lane) {
    float4 ev = ((const float4*)(embed + (size_t)k * DIM))[lane];
    float s = xv.x * ev.x;
    s = fmaf(xv.y, ev.y, s);
    s = fmaf(xv.z, ev.z, s);
    s = fmaf(xv.w, ev.w, s);
    #pragma unroll
    for (int o = 16; o > 0; o >>= 1) s += __shfl_xor_sync(0xffffffffu, s, o);
    return fmaf(2.f, s, -__ldg(&g_esq[k]));
}

// ---------------------------------------------------------------------------
// Kernel 1: e_sq per code, zero class accumulators, write fp16(embed) into
// m16n8k16 B-fragment order, tile-major (BN=32).
//  For code n, k: ct=n>>5, wn=(n>>4)&1, nt=(n>>3)&1, lane=(n&7)*4+((k&7)>>1),
//  ks=k>>4, reg=(k>>3)&1, half=k&1.
//  u32 index = (ct*1024 + ((wn*2+nt)*8+ks)*32 + lane)*2 + reg
// ---------------------------------------------------------------------------
__global__ void prep_kernel(const float* __restrict__ embed) {
    const int tid  = blockIdx.x * blockDim.x + threadIdx.x;  // 0..65535
    const int lane = tid & 31;
    const int warp = tid >> 5;
    if (tid < KCODES) g_clsum[tid] = 0.f;

    {   // e_sq, warp per code
        const float* row = embed + (size_t)warp * DIM;
        float s = 0.f;
        #pragma unroll
        for (int i = 0; i < 4; ++i) { float v = row[lane + 32 * i]; s = fmaf(v, v, s); }
        #pragma unroll
        for (int o = 16; o > 0; o >>= 1) s += __shfl_down_sync(0xffffffffu, s, o);
        if (lane == 0) g_esq[warp] = s;
    }

    {   // B fragment scatter: one float4 (k0..k0+3) per thread
        float4 v = ((const float4*)embed)[tid];
        const int n  = tid >> 5;
        const int k0 = (tid & 31) * 4;
        const int ct = n >> 5;
        const int wn = (n >> 4) & 1;
        const int nt = (n >> 3) & 1;
        const int ln = (n & 7) * 4 + ((k0 & 7) >> 1);
        const int ks = k0 >> 4;
        const int rg = (k0 >> 3) & 1;
        __half2 h01 = __floats2half2_rn(v.x, v.y);
        __half2 h23 = __floats2half2_rn(v.z, v.w);
        int u2 = ct * 1024 + ((wn * 2 + nt) * 8 + ks) * 32 + ln;
        g_bh[(size_t)u2 * 2 + rg]       = *(uint32_t*)&h01;
        g_bh[(size_t)(u2 + 1) * 2 + rg] = *(uint32_t*)&h23;
    }
}

// ---------------------------------------------------------------------------
// Kernel 2: fp16 m16n8k16 GEMM (A fragments in registers) + fp16 conf spill
// + argmax w/ warp-cooperative exact rescue + fused softmax + gather.
// ---------------------------------------------------------------------------
__global__ void __launch_bounds__(256, 2)
gemm_kernel(const float* __restrict__ x,
            const float* __restrict__ embed,
            float* __restrict__ out_q,
            float* __restrict__ out_ind) {
    extern __shared__ float sm[];
    uint32_t* AF32 = (uint32_t*)sm;          // staging, 8192 u32
    uint4*    AF4  = (uint4*)sm;
    uint2*    BS2  = (uint2*)(sm + B_S);     // 2 stages x 1024 uint2

    const int tid  = threadIdx.x;
    const int lane = tid & 31;
    const int w    = tid >> 5;
    const int wm   = w >> 1;          // 0..3: 32-point slab
    const int wn   = w & 1;           // 0..1: 16-code slab
    const int n0   = blockIdx.x * BM;

    const uint32_t b_s = (uint32_t)__cvta_generic_to_shared(sm + B_S);

    // ---- issue B tile 0 copy (8KB) ----
    {
        const float4* g4 = (const float4*)g_bh;
        cp_async16(b_s + tid * 16,        &g4[tid]);
        cp_async16(b_s + 4096 + tid * 16, &g4[256 + tid]);
        asm volatile("cp.async.commit_group;");
    }

    // ---- A fragment staging: fp16(2*x) into m16n8k16 A-fragment order ----
    {
        const float4* x4 = (const float4*)(x + (size_t)n0 * DIM);
        #pragma unroll
        for (int t = 0; t < 16; ++t) {
            int idx = t * 256 + tid;
            int m   = idx >> 5;
            int k0  = (idx & 31) * 4;
            float4 v = x4[idx];
            __half2 h01 = __floats2half2_rn(2.f * v.x, 2.f * v.y);
            __half2 h23 = __floats2half2_rn(2.f * v.z, 2.f * v.w);
            int u4 = (((m >> 5) * 2 + ((m >> 4) & 1)) * 8 + (k0 >> 4)) * 32
                     + (m & 7) * 4 + ((k0 & 7) >> 1);
            int rg = ((m & 15) >> 3) + (((k0 >> 3) & 1) << 1);
            AF32[u4 * 4 + rg]       = *(uint32_t*)&h01;
            AF32[(u4 + 1) * 4 + rg] = *(uint32_t*)&h23;
        }
    }
    __syncthreads();

    // ---- load this warp's A fragments into registers (64 regs) ----
    uint4 af[2][8];
    #pragma unroll
    for (int mt = 0; mt < 2; ++mt)
        #pragma unroll
        for (int ks = 0; ks < 8; ++ks)
            af[mt][ks] = AF4[((wm * 2 + mt) * 8 + ks) * 32 + lane];

    float runv[4];
    int   runi[4];
    #pragma unroll
    for (int i = 0; i < 4; ++i) { runv[i] = -3.0e38f; runi[i] = 0; }

    for (int ct = 0; ct < NTILES; ++ct) {
        if (ct + 1 < NTILES) {
            const float4* g4 = (const float4*)g_bh + (size_t)(ct + 1) * 512;
            uint32_t dst = b_s + (uint32_t)(((ct + 1) & 1) * 8192);
            cp_async16(dst + tid * 16,        &g4[tid]);
            cp_async16(dst + 4096 + tid * 16, &g4[256 + tid]);
            asm volatile("cp.async.commit_group;");
            asm volatile("cp.async.wait_group 1;");
        } else {
            asm volatile("cp.async.wait_group 0;");
        }
        __syncthreads();                      // stage (ct&1) visible to all warps

        const uint2* bs = BS2 + (ct & 1) * 1024;

        float acc[2][2][4];
        #pragma unroll
        for (int mt = 0; mt < 2; ++mt)
            #pragma unroll
            for (int nt = 0; nt < 2; ++nt)
                #pragma unroll
                for (int r = 0; r < 4; ++r) acc[mt][nt][r] = 0.f;

        #pragma unroll
        for (int ks = 0; ks < 8; ++ks) {
            uint2 b0 = bs[((wn * 2 + 0) * 8 + ks) * 32 + lane];
            uint2 b1 = bs[((wn * 2 + 1) * 8 + ks) * 32 + lane];
            MMA_F16(acc[0][0], af[0][ks], b0);
            MMA_F16(acc[0][1], af[0][ks], b1);
            MMA_F16(acc[1][0], af[1][ks], b0);
            MMA_F16(acc[1][1], af[1][ks], b1);
        }

        // ---- epilogue: conf = acc - esq, running argmax, fp16 spill ----
        const int c0 = ct * BN;
        #pragma unroll
        for (int nt = 0; nt < 2; ++nt) {
            int cb = c0 + wn * 16 + nt * 8 + 2 * (lane & 3);
            float e0 = __ldg(&g_esq[cb]);
            float e1 = __ldg(&g_esq[cb + 1]);
            #pragma unroll
            for (int mt = 0; mt < 2; ++mt) {
                #pragma unroll
                for (int h = 0; h < 2; ++h) {
                    int slot = mt * 2 + h;
                    int row  = n0 + wm * 32 + mt * 16 + (lane >> 2) + h * 8;
                    float v0 = acc[mt][nt][2 * h + 0] - e0;
                    float v1 = acc[mt][nt][2 * h + 1] - e1;
                    if (v0 > runv[slot]) { runv[slot] = v0; runi[slot] = cb; }
                    if (v1 > runv[slot]) { runv[slot] = v1; runi[slot] = cb + 1; }
                    *(__half2*)&g_conf[(size_t)row * KCODES + cb] =
                        __floats2half2_rn(v0, v1);
                }
            }
        }
        __syncthreads();                      // stage safe to overwrite
    }

    // ---- cross-thread argmax reduction (8 contributors per point) ----
    float* red_v  = sm + RED_V;
    int*   red_i  = (int*)(sm + RED_I);
    int*   sidx   = (int*)(sm + SIDX);
    float* maxv_s = sm + MAXV;
    float* zinv   = sm + ZINV;
    float* bins_s = sm + BINS;
    #pragma unroll
    for (int mt = 0; mt < 2; ++mt)
        #pragma unroll
        for (int h = 0; h < 2; ++h) {
            int slot = mt * 2 + h;
            int rloc = wm * 32 + mt * 16 + (lane >> 2) + h * 8;
            int cidx = wn * 4 + (lane & 3);
            red_v[rloc * 8 + cidx] = runv[slot];
            red_i[rloc * 8 + cidx] = runi[slot];
        }
    __syncthreads();
    if (tid < BM) {
        float bv = red_v[tid * 8];
        int   bi = red_i[tid * 8];
        #pragma unroll
        for (int t = 1; t < 8; ++t) {
            float v  = red_v[tid * 8 + t];
            int   ii = red_i[tid * 8 + t];
            if (v > bv || (v == bv && ii < bi)) { bv = v; bi = ii; }
        }
        maxv_s[tid] = bv;
        sidx[tid]   = bi;
    }
    if (tid < KCODES / 8) {
        #pragma unroll
        for (int r = 0; r < 8; ++r) bins_s[r * 256 + tid] = 0.f;
    }
    __syncthreads();

    // ---- fused softmax on fp16 conf (warp per point) + warp-coop rescue ----
    {
        float* eb = sm + EB_S;             // [8][KCODES]
        for (int it = 0; it < BM / 8; ++it) {
            const int pl = it * 8 + w;
            const float m = maxv_s[pl];
            const int   am = sidx[pl];
            const float thresh = m - 2.0f;
            const uint4* row16 = (const uint4*)&g_conf[(size_t)(n0 + pl) * KCODES];

            uint32_t cm0 = 0u, cm1 = 0u;
            float z = 0.f;
            #pragma unroll
            for (int j = 0; j < 8; ++j) {
                uint4 u = row16[j * 32 + lane];
                float c[8];
                {
                    float2 f0 = __half22float2(*(__half2*)&u.x);
                    float2 f1 = __half22float2(*(__half2*)&u.y);
                    float2 f2 = __half22float2(*(__half2*)&u.z);
                    float2 f3 = __half22float2(*(__half2*)&u.w);
                    c[0] = f0.x; c[1] = f0.y; c[2] = f1.x; c[3] = f1.y;
                    c[4] = f2.x; c[5] = f2.y; c[6] = f3.x; c[7] = f3.y;
                }
                int kb = j * 256 + lane * 8;
                float e[8];
                uint32_t mbits = 0u;
                #pragma unroll
                for (int t = 0; t < 8; ++t) {
                    e[t] = __expf((c[t] - m) * TEMP_INV);
                    z += e[t];
                    if (c[t] >= thresh && kb + t != am) mbits |= (1u << t);
                }
                *(float4*)&eb[w * KCODES + kb]     = make_float4(e[0], e[1], e[2], e[3]);
                *(float4*)&eb[w * KCODES + kb + 4] = make_float4(e[4], e[5], e[6], e[7]);
                if (j < 4) cm0 |= mbits << (j * 8);
                else       cm1 |= mbits << ((j - 4) * 8);
            }
            #pragma unroll
            for (int o = 16; o > 0; o >>= 1) z += __shfl_xor_sync(0xffffffffu, z, o);
            if (lane == 0) zinv[w] = 1.f / z;

            if (__ballot_sync(0xffffffffu, (cm0 | cm1) != 0u) != 0u) {
                float4 xv = ((const float4*)(x + (size_t)(n0 + pl) * DIM))[lane];
                float bv = warp_conf(xv, embed, am, lane);
                int   bi = am;
                for (;;) {
                    uint32_t have = __ballot_sync(0xffffffffu, (cm0 | cm1) != 0u);
                    if (!have) break;
                    int src = __ffs(have) - 1;
                    int kc = 0;
                    if (lane == src) {
                        if (cm0) {
                            int b = __ffs(cm0) - 1; cm0 &= cm0 - 1;
                            kc = (b >> 3) * 256 + lane * 8 + (b & 7);
                        } else {
                            int b = __ffs(cm1) - 1; cm1 &= cm1 - 1;
                            kc = 1024 + (b >> 3) * 256 + lane * 8 + (b & 7);
                        }
                    }
                    kc = __shfl_sync(0xffffffffu, kc, src);
                    float v = warp_conf(xv, embed, kc, lane);
                    if (v > bv || (v == bv && kc < bi)) { bv = v; bi = kc; }
                }
                if (lane == 0) sidx[pl] = bi;
            }
            __syncthreads();

            for (int k = tid; k < KCODES; k += 256) {
                float s = 0.f;
                #pragma unroll
                for (int ww = 0; ww < 8; ++ww) s = fmaf(eb[ww * KCODES + k], zinv[ww], s);
                bins_s[k] += s;
            }
            __syncthreads();
        }
    }

    // ---- ind write + gather with rescued indices + bins flush ----
    if (tid < BM) out_ind[n0 + tid] = (float)sidx[tid];
    {
        const float4* e4 = (const float4*)embed;
        float4*       q4 = (float4*)out_q;
        for (int p = w; p < BM; p += 8) {
            int idx = sidx[p];
            q4[(size_t)(n0 + p) * 32 + lane] = e4[(size_t)idx * 32 + lane];
        }
    }
    for (int k = tid; k < KCODES; k += 256) atomicAdd(&g_clsum[k], bins_s[k]);
}

// ---------------------------------------------------------------------------
// Kernel 3: diversity loss = sum_k p_k * log(p_k + eps).
// ---------------------------------------------------------------------------
__global__ void loss_kernel(float* __restrict__ out_loss) {
    __shared__ float red[256];
    const int tid = threadIdx.x;
    float acc = 0.f;
    for (int k = tid; k < KCODES; k += 256) {
        float p = g_clsum[k] * (1.0f / (float)N_PTS);
        acc += p * __logf(p + 1e-6f);
    }
    red[tid] = acc;
    __syncthreads();
    for (int s = 128; s > 0; s >>= 1) {
        if (tid < s) red[tid] += red[tid + s];
        __syncthreads();
    }
    if (tid == 0) *out_loss = red[0];
}

// ---------------------------------------------------------------------------
extern "C" void kernel_launch(void* const* d_in, const int* in_sizes, int n_in,
                              void* d_out, int out_size) {
    const float* x     = (const float*)d_in[0];
    const float* embed = (const float*)d_in[1];
    float* out      = (float*)d_out;
    float* out_q    = out;                                   // N*DIM
    float* out_ind  = out + (size_t)N_PTS * DIM;             // N
    float* out_loss = out + (size_t)N_PTS * DIM + N_PTS;     // 1

    const int gemm_smem = SMEM_FLOATS * (int)sizeof(float);  // ~84 KB
    cudaFuncSetAttribute(gemm_kernel, cudaFuncAttributeMaxDynamicSharedMemorySize, gemm_smem);

    prep_kernel <<<256, 256>>>(embed);
    gemm_kernel <<<N_PTS / BM, 256, gemm_smem>>>(x, embed, out_q, out_ind);
    loss_kernel <<<1, 256>>>(out_loss);
}